// round 15
// baseline (speedup 1.0000x reference)
#include <cuda_runtime.h>
#include <cuda_fp16.h>
#include <stdint.h>
#include <math.h>

#define S_LEN   2048
#define DM      4096
#define NQ      32
#define NKV     8
#define HD      128
#define WINDOW  1024
#define KDIM    4096
#define NCH     (KDIM / 64)

// ---------------- scratch (__device__ globals; allocation-free rule) -------
__device__ __align__(16) float g_Q[S_LEN * NQ * HD];
__device__ __align__(16) float g_K[S_LEN * NKV * HD];
__device__ __align__(16) float g_V[S_LEN * NKV * HD];
__device__ __align__(16) float g_A[S_LEN * NQ * HD];

__device__ __align__(16) __half g_xh[S_LEN * DM], g_xl[S_LEN * DM];
__device__ __align__(16) __half g_wqh[DM * DM];
__device__ __align__(16) __half g_wkh[NKV * HD * DM];
__device__ __align__(16) __half g_wvh[NKV * HD * DM];
__device__ __align__(16) __half g_woh[DM * DM];
__device__ __align__(16) __half g_ah[S_LEN * DM], g_al[S_LEN * DM];

// ---------------------------- PTX helpers ----------------------------------
__device__ __forceinline__ uint32_t smem_u32(const void* p) {
    uint32_t a;
    asm("{ .reg .u64 t; cvta.to.shared.u64 t, %1; cvt.u32.u64 %0, t; }"
        : "=r"(a) : "l"(p));
    return a;
}

#define SWZ(x) ((x) ^ (((x) >> 3) & 0x70))

__device__ __forceinline__ void cpasync16(uint32_t sa, const void* g) {
    asm volatile("cp.async.cg.shared.global [%0], [%1], 16;" ::"r"(sa), "l"(g)
                 : "memory");
}

__device__ __forceinline__ void ldsm4(uint32_t* r, uint32_t a) {
    asm volatile(
        "ldmatrix.sync.aligned.m8n8.x4.shared.b16 {%0,%1,%2,%3}, [%4];"
        : "=r"(r[0]), "=r"(r[1]), "=r"(r[2]), "=r"(r[3]) : "r"(a));
}

__device__ __forceinline__ void mma16816(float* d, const uint32_t* a,
                                         const uint32_t* b) {
    asm volatile(
        "mma.sync.aligned.m16n8k16.row.col.f32.f16.f16.f32 "
        "{%0,%1,%2,%3},{%4,%5,%6,%7},{%8,%9},{%0,%1,%2,%3};"
        : "+f"(d[0]), "+f"(d[1]), "+f"(d[2]), "+f"(d[3])
        : "r"(a[0]), "r"(a[1]), "r"(a[2]), "r"(a[3]), "r"(b[0]), "r"(b[1]));
}

// ---------------------------------------------------------------------------
// Tensor-core GEMM (unchanged from R10/13): fp16 2-term split.
// ---------------------------------------------------------------------------
#define STAGE_BYTES (3 * 16384)
#define GEMM_SMEM   (3 * STAGE_BYTES)

__global__ __launch_bounds__(256, 1)
void gemm_tc(const __half* __restrict__ Ah,
             const __half* __restrict__ Al,
             const __half* __restrict__ Bh,
             float* __restrict__ C, int ldc)
{
    extern __shared__ char smem[];
    const uint32_t sb = smem_u32(smem);
    const int tid  = threadIdx.x;
    const int wid  = tid >> 5;
    const int lane = tid & 31;
    const int m0   = blockIdx.y * 128;
    const int n0   = blockIdx.x * 128;

    const int warp_m = (wid & 3) * 32;
    const int warp_n = (wid >> 2) * 64;

    const __half* gb[3] = {
        Ah + (size_t)m0 * KDIM, Al + (size_t)m0 * KDIM,
        Bh + (size_t)n0 * KDIM };

    auto stage = [&](int ck) {
        const uint32_t base = sb + (ck % 3) * STAGE_BYTES;
#pragma unroll
        for (int j = 0; j < 12; j++) {
            const int i   = tid + j * 256;
            const int a   = i >> 10;
            const int rem = i & 1023;
            const int row = rem >> 3;
            const int c16 = rem & 7;
            cpasync16(base + a * 16384 + SWZ(row * 128 + c16 * 16),
                      gb[a] + (size_t)row * KDIM + ck * 64 + c16 * 8);
        }
        asm volatile("cp.async.commit_group;" ::: "memory");
    };

    float acc[2][8][4];
#pragma unroll
    for (int t = 0; t < 2; t++)
#pragma unroll
        for (int n = 0; n < 8; n++)
#pragma unroll
            for (int j = 0; j < 4; j++) acc[t][n][j] = 0.f;

    const int a_row  = warp_m + (lane & 15);
    const int a_half = lane >> 4;
    const int b_row  = warp_n + ((lane >> 4) & 1) * 8 + (lane & 7);
    const int b_half = (lane >> 3) & 1;

    stage(0);
    stage(1);

    for (int c = 0; c < NCH; c++) {
        asm volatile("cp.async.wait_group 1;" ::: "memory");
        __syncthreads();
        if (c + 2 < NCH) stage(c + 2);
        else asm volatile("cp.async.commit_group;" ::: "memory");

        const uint32_t bAh = sb + (c % 3) * STAGE_BYTES;
        const uint32_t bAl = bAh + 16384;
        const uint32_t bBh = bAh + 32768;

#pragma unroll
        for (int ks = 0; ks < 4; ks++) {
            uint32_t ah[2][4], al[2][4], bh[4][4];
#pragma unroll
            for (int t = 0; t < 2; t++) {
                const int r  = a_row + t * 16;
                const uint32_t off =
                    r * 128 + (((ks * 2 + a_half) ^ (r & 7)) * 16);
                ldsm4(ah[t], bAh + off);
                ldsm4(al[t], bAl + off);
            }
#pragma unroll
            for (int p = 0; p < 4; p++) {
                const int r  = b_row + p * 16;
                const uint32_t off =
                    r * 128 + (((ks * 2 + b_half) ^ (r & 7)) * 16);
                ldsm4(bh[p], bBh + off);
            }
#pragma unroll
            for (int t = 0; t < 2; t++)
#pragma unroll
                for (int n = 0; n < 8; n++) {
                    const uint32_t* bhp = &bh[n >> 1][(n & 1) * 2];
                    mma16816(acc[t][n], ah[t], bhp);
                    mma16816(acc[t][n], al[t], bhp);
                }
        }
    }
    __syncthreads();

    const int g  = lane >> 2;
    const int tg = lane & 3;
#pragma unroll
    for (int t = 0; t < 2; t++)
#pragma unroll
        for (int n = 0; n < 8; n++) {
            const int col = n0 + warp_n + n * 8 + tg * 2;
            float* d0 = C + (size_t)(m0 + warp_m + t * 16 + g) * ldc + col;
            float* d1 = C + (size_t)(m0 + warp_m + t * 16 + g + 8) * ldc + col;
            *(float2*)d0 = make_float2(acc[t][n][0], acc[t][n][1]);
            *(float2*)d1 = make_float2(acc[t][n][2], acc[t][n][3]);
        }
}

// ---------------------------------------------------------------------------
// fp32 -> (hi, lo) fp16 split, elementwise
// ---------------------------------------------------------------------------
__global__ void split_kernel(const float4* __restrict__ in,
                             __half2* __restrict__ hi,
                             __half2* __restrict__ lo, int n4)
{
    int i = blockIdx.x * blockDim.x + threadIdx.x;
    if (i >= n4) return;
    float4 v = in[i];
    __half hx = __float2half(v.x), hy = __float2half(v.y);
    __half hz = __float2half(v.z), hw = __float2half(v.w);
    __half lx = __float2half(v.x - __half2float(hx));
    __half ly = __float2half(v.y - __half2float(hy));
    __half lz = __float2half(v.z - __half2float(hz));
    __half lw = __float2half(v.w - __half2float(hw));
    hi[2 * i]     = __halves2half2(hx, hy);
    hi[2 * i + 1] = __halves2half2(hz, hw);
    lo[2 * i]     = __halves2half2(lx, ly);
    lo[2 * i + 1] = __halves2half2(lz, lw);
}

// ---------------------------------------------------------------------------
// W[K,N] fp32 -> W^T hi fp16 [N,K]  (tiled transpose, hi only)
// ---------------------------------------------------------------------------
__global__ void tsplit_kernel(const float* __restrict__ W,
                              __half* __restrict__ Th, int K, int N)
{
    __shared__ float t[32][33];
    const int n0 = blockIdx.x * 32, k0 = blockIdx.y * 32;
    const int tx = threadIdx.x, ty = threadIdx.y;   // (32, 8)
#pragma unroll
    for (int j = 0; j < 32; j += 8)
        t[ty + j][tx] = W[(size_t)(k0 + ty + j) * N + n0 + tx];
    __syncthreads();
#pragma unroll
    for (int j = 0; j < 32; j += 8) {
        const int r = ty + j;
        Th[(size_t)(n0 + r) * K + k0 + tx] = __float2half(t[tx][r]);
    }
}

// ---------------------------------------------------------------------------
// RoPE in-place on T laid out [S, nheads*HD]
// ---------------------------------------------------------------------------
__global__ void rope_kernel(float* __restrict__ T,
                            const float* __restrict__ cosT,
                            const float* __restrict__ sinT,
                            int nheads, int total)
{
    int idx = blockIdx.x * blockDim.x + threadIdx.x;
    if (idx >= total) return;
    int i = idx & 63;
    int h = (idx >> 6) % nheads;
    int s = idx / (nheads * 64);
    float c  = cosT[s * 64 + i];
    float sn = sinT[s * 64 + i];
    float* p = T + (size_t)s * nheads * HD + h * HD + 2 * i;
    float e = p[0], o = p[1];
    p[0] = e * c - o * sn;
    p[1] = e * sn + o * c;
}

// ---------------------------------------------------------------------------
// Sliding-window causal GQA attention (fp32 flash-style), restructured:
// fully-unrolled phases with independent chains:
//   1) 2x16 partial dots (2-way split accumulators, j-parallel)
//   2) batched butterfly shuffles (independent)
//   3) mask/scale/max, sp[] register-resident (constant indices only)
//   4) PV: 32 independent broadcast shuffles + ILP-32 FMA accumulation
// ---------------------------------------------------------------------------
__global__ __launch_bounds__(256, 2) void attn_kernel(
    const float* __restrict__ Q, const float* __restrict__ K,
    const float* __restrict__ V, float* __restrict__ O)
{
    __shared__ __align__(16) float Ksm[32][HD];
    __shared__ __align__(16) float Vsm[32][HD];

    const int h    = blockIdx.x;
    const int q0   = blockIdx.y * 64;
    const int tid  = threadIdx.x;
    const int lane = tid & 31;
    const int row  = tid >> 2;
    const int p    = tid & 3;
    const int q    = q0 + row;
    const int kvh  = h >> 2;
    const float scale = 0.08838834764831845f;

    float4 qv[8];
    {
        const float4* qp =
            (const float4*)(Q + (size_t)q * (NQ * HD) + h * HD + p * 32);
#pragma unroll
        for (int i = 0; i < 8; i++) qv[i] = qp[i];
    }

    float4 o4[8];
#pragma unroll
    for (int i = 0; i < 8; i++) o4[i] = make_float4(0.f, 0.f, 0.f, 0.f);
    float m = -5e29f, l = 0.f;

    int kv_begin = q0 - WINDOW + 1;
    if (kv_begin < 0) kv_begin = 0;
    kv_begin &= ~31;

    for (int kv0 = kv_begin; kv0 < q0 + 64; kv0 += 32) {
        __syncthreads();
        for (int i = tid; i < 32 * HD / 4; i += 256) {
            int r = i >> 5;
            int c = (i & 31) * 4;
            size_t g = (size_t)(kv0 + r) * (NKV * HD) + kvh * HD + c;
            *(float4*)&Ksm[r][c] = *(const float4*)&K[g];
            *(float4*)&Vsm[r][c] = *(const float4*)&V[g];
        }
        __syncthreads();

        float sp[8];
        float tm = -5e29f;

#pragma unroll
        for (int half = 0; half < 2; half++) {
            float s[16];
            // phase 1: 16 independent partial dots (chain depth 16)
#pragma unroll
            for (int jj = 0; jj < 16; jj++) {
                const int j = half * 16 + jj;
                const float4* kr = (const float4*)&Ksm[j][p * 32];
                float s0 = 0.f, s1 = 0.f;
#pragma unroll
                for (int i = 0; i < 8; i += 2) {
                    float4 k4 = kr[i];
                    float4 k5 = kr[i + 1];
                    s0 = fmaf(qv[i].x, k4.x, s0);
                    s0 = fmaf(qv[i].y, k4.y, s0);
                    s0 = fmaf(qv[i].z, k4.z, s0);
                    s0 = fmaf(qv[i].w, k4.w, s0);
                    s1 = fmaf(qv[i + 1].x, k5.x, s1);
                    s1 = fmaf(qv[i + 1].y, k5.y, s1);
                    s1 = fmaf(qv[i + 1].z, k5.z, s1);
                    s1 = fmaf(qv[i + 1].w, k5.w, s1);
                }
                s[jj] = s0 + s1;
            }
            // phase 2: independent butterfly reductions
#pragma unroll
            for (int jj = 0; jj < 16; jj++)
                s[jj] += __shfl_xor_sync(0xffffffffu, s[jj], 1);
#pragma unroll
            for (int jj = 0; jj < 16; jj++)
                s[jj] += __shfl_xor_sync(0xffffffffu, s[jj], 2);
            // phase 3: mask/scale, track max, keep own lane's 4 scores
#pragma unroll
            for (int jj = 0; jj < 16; jj++) {
                const int j = half * 16 + jj;
                const int dlt = q - (kv0 + j);
                const float v =
                    (dlt >= 0 && dlt < WINDOW) ? s[jj] * scale : -1e30f;
                if ((j & 3) == p) sp[half * 4 + (jj >> 2)] = v;
                tm = fmaxf(tm, v);
            }
        }

        const float newm  = fmaxf(m, tm);
        const float alpha = __expf(m - newm);
        float psum = 0.f;
#pragma unroll
        for (int jj = 0; jj < 8; jj++) {
            sp[jj] = __expf(sp[jj] - newm);
            psum += sp[jj];
        }
        psum += __shfl_xor_sync(0xffffffffu, psum, 1);
        psum += __shfl_xor_sync(0xffffffffu, psum, 2);
        l = l * alpha + psum;
#pragma unroll
        for (int i = 0; i < 8; i++) {
            o4[i].x *= alpha; o4[i].y *= alpha;
            o4[i].z *= alpha; o4[i].w *= alpha;
        }
        m = newm;

        // phase 4: PV — fully unrolled, sp indices constant, shuffles indep.
#pragma unroll
        for (int j = 0; j < 32; j++) {
            const float pj = __shfl_sync(0xffffffffu, sp[j >> 2],
                                         (lane & ~3) | (j & 3));
            const float4* vr = (const float4*)&Vsm[j][p * 32];
#pragma unroll
            for (int i = 0; i < 8; i++) {
                float4 v4 = vr[i];
                o4[i].x = fmaf(pj, v4.x, o4[i].x);
                o4[i].y = fmaf(pj, v4.y, o4[i].y);
                o4[i].z = fmaf(pj, v4.z, o4[i].z);
                o4[i].w = fmaf(pj, v4.w, o4[i].w);
            }
        }
    }

    const float inv = 1.f / l;
    float4* op = (float4*)(O + (size_t)q * (NQ * HD) + h * HD + p * 32);
#pragma unroll
    for (int i = 0; i < 8; i++)
        op[i] = make_float4(o4[i].x * inv, o4[i].y * inv,
                            o4[i].z * inv, o4[i].w * inv);
}

// ---------------------------------------------------------------------------
extern "C" void kernel_launch(void* const* d_in, const int* in_sizes, int n_in,
                              void* d_out, int out_size)
{
    const float* x  = (const float*)d_in[0];
    const float* fc = (const float*)d_in[1];
    const float* fs = (const float*)d_in[2];
    const float* wq = (const float*)d_in[4];
    const float* wk = (const float*)d_in[5];
    const float* wv = (const float*)d_in[6];
    const float* wo = (const float*)d_in[7];
    float* out = (float*)d_out;

    float *Qb, *Kb, *Vb, *Ab;
    cudaGetSymbolAddress((void**)&Qb, g_Q);
    cudaGetSymbolAddress((void**)&Kb, g_K);
    cudaGetSymbolAddress((void**)&Vb, g_V);
    cudaGetSymbolAddress((void**)&Ab, g_A);

    __half *xh, *xl, *wqh, *wkh, *wvh, *woh, *ah, *al;
    cudaGetSymbolAddress((void**)&xh,  g_xh);
    cudaGetSymbolAddress((void**)&xl,  g_xl);
    cudaGetSymbolAddress((void**)&wqh, g_wqh);
    cudaGetSymbolAddress((void**)&wkh, g_wkh);
    cudaGetSymbolAddress((void**)&wvh, g_wvh);
    cudaGetSymbolAddress((void**)&woh, g_woh);
    cudaGetSymbolAddress((void**)&ah,  g_ah);
    cudaGetSymbolAddress((void**)&al,  g_al);

    cudaFuncSetAttribute(gemm_tc, cudaFuncAttributeMaxDynamicSharedMemorySize,
                         GEMM_SMEM);

    {
        int n4 = S_LEN * DM / 4;
        split_kernel<<<(n4 + 255) / 256, 256>>>((const float4*)x,
            (__half2*)xh, (__half2*)xl, n4);                                 // 0
    }
    tsplit_kernel<<<dim3(DM / 32, DM / 32), dim3(32, 8)>>>(wq, wqh, DM, DM);                 // 1
    tsplit_kernel<<<dim3((NKV * HD) / 32, DM / 32), dim3(32, 8)>>>(wk, wkh, DM, NKV * HD);   // 2

    gemm_tc<<<dim3(DM / 128, S_LEN / 128), 256, GEMM_SMEM>>>(xh, xl, wqh, Qb, DM);           // 3 (profiled)

    tsplit_kernel<<<dim3((NKV * HD) / 32, DM / 32), dim3(32, 8)>>>(wv, wvh, DM, NKV * HD);   // 4
    gemm_tc<<<dim3((NKV * HD) / 128, S_LEN / 128), 256, GEMM_SMEM>>>(xh, xl, wkh, Kb, NKV * HD); // 5
    gemm_tc<<<dim3((NKV * HD) / 128, S_LEN / 128), 256, GEMM_SMEM>>>(xh, xl, wvh, Vb, NKV * HD); // 6
    tsplit_kernel<<<dim3(DM / 32, DM / 32), dim3(32, 8)>>>(wo, woh, DM, DM);                 // 7

    {
        int totq = S_LEN * NQ * (HD / 2);
        int totk = S_LEN * NKV * (HD / 2);
        rope_kernel<<<(totq + 255) / 256, 256>>>(Qb, fc, fs, NQ, totq);      // 8
        rope_kernel<<<(totk + 255) / 256, 256>>>(Kb, fc, fs, NKV, totk);     // 9
    }

    attn_kernel<<<dim3(NQ, S_LEN / 64), 256>>>(Qb, Kb, Vb, Ab);              // 10

    {
        int n4 = S_LEN * DM / 4;
        split_kernel<<<(n4 + 255) / 256, 256>>>((const float4*)Ab,
            (__half2*)ah, (__half2*)al, n4);                                 // 11
    }
    gemm_tc<<<dim3(DM / 128, S_LEN / 128), 256, GEMM_SMEM>>>(ah, al, woh, out, DM);          // 12
}

// round 16
// speedup vs baseline: 6.0688x; 6.0688x over previous
#include <cuda_runtime.h>
#include <cuda_fp16.h>
#include <stdint.h>
#include <math.h>

#define S_LEN   2048
#define DM      4096
#define NQ      32
#define NKV     8
#define HD      128
#define WINDOW  1024
#define KDIM    4096
#define NCH     (KDIM / 64)

// ---------------- scratch (__device__ globals; allocation-free rule) -------
__device__ __align__(16) float g_Q[S_LEN * NQ * HD];
__device__ __align__(16) float g_K[S_LEN * NKV * HD];
__device__ __align__(16) float g_V[S_LEN * NKV * HD];
__device__ __align__(16) float g_A[S_LEN * NQ * HD];

__device__ __align__(16) __half g_xh[S_LEN * DM], g_xl[S_LEN * DM];
__device__ __align__(16) __half g_wqh[DM * DM];
__device__ __align__(16) __half g_wkh[NKV * HD * DM];
__device__ __align__(16) __half g_wvh[NKV * HD * DM];
__device__ __align__(16) __half g_woh[DM * DM];
__device__ __align__(16) __half g_ah[S_LEN * DM], g_al[S_LEN * DM];

__device__ __align__(16) __half g_qh[S_LEN * NQ * HD],  g_ql[S_LEN * NQ * HD];
__device__ __align__(16) __half g_kh[S_LEN * NKV * HD], g_kl[S_LEN * NKV * HD];
__device__ __align__(16) __half g_vh[S_LEN * NKV * HD], g_vl[S_LEN * NKV * HD];

// ---------------------------- PTX helpers ----------------------------------
__device__ __forceinline__ uint32_t smem_u32(const void* p) {
    uint32_t a;
    asm("{ .reg .u64 t; cvta.to.shared.u64 t, %1; cvt.u32.u64 %0, t; }"
        : "=r"(a) : "l"(p));
    return a;
}

#define SWZ(x) ((x) ^ (((x) >> 3) & 0x70))

// 256B-row swizzle: two 128B halves, 16B units xor'ed by row&7
__device__ __forceinline__ uint32_t swz256(int row, int c16) {
    return row * 256 + ((c16 & 8) << 4) + ((((c16 & 7) ^ (row & 7))) << 4);
}

__device__ __forceinline__ void cpasync16(uint32_t sa, const void* g) {
    asm volatile("cp.async.cg.shared.global [%0], [%1], 16;" ::"r"(sa), "l"(g)
                 : "memory");
}

__device__ __forceinline__ void ldsm4(uint32_t* r, uint32_t a) {
    asm volatile(
        "ldmatrix.sync.aligned.m8n8.x4.shared.b16 {%0,%1,%2,%3}, [%4];"
        : "=r"(r[0]), "=r"(r[1]), "=r"(r[2]), "=r"(r[3]) : "r"(a));
}

__device__ __forceinline__ void ldsm4t(uint32_t* r, uint32_t a) {
    asm volatile(
        "ldmatrix.sync.aligned.m8n8.x4.trans.shared.b16 {%0,%1,%2,%3}, [%4];"
        : "=r"(r[0]), "=r"(r[1]), "=r"(r[2]), "=r"(r[3]) : "r"(a));
}

__device__ __forceinline__ void mma16816(float* d, const uint32_t* a,
                                         const uint32_t* b) {
    asm volatile(
        "mma.sync.aligned.m16n8k16.row.col.f32.f16.f16.f32 "
        "{%0,%1,%2,%3},{%4,%5,%6,%7},{%8,%9},{%0,%1,%2,%3};"
        : "+f"(d[0]), "+f"(d[1]), "+f"(d[2]), "+f"(d[3])
        : "r"(a[0]), "r"(a[1]), "r"(a[2]), "r"(a[3]), "r"(b[0]), "r"(b[1]));
}

// ---------------------------------------------------------------------------
// Tensor-core GEMM (unchanged): fp16 2-term split.
// ---------------------------------------------------------------------------
#define STAGE_BYTES (3 * 16384)
#define GEMM_SMEM   (3 * STAGE_BYTES)

__global__ __launch_bounds__(256, 1)
void gemm_tc(const __half* __restrict__ Ah,
             const __half* __restrict__ Al,
             const __half* __restrict__ Bh,
             float* __restrict__ C, int ldc)
{
    extern __shared__ char smem[];
    const uint32_t sb = smem_u32(smem);
    const int tid  = threadIdx.x;
    const int wid  = tid >> 5;
    const int lane = tid & 31;
    const int m0   = blockIdx.y * 128;
    const int n0   = blockIdx.x * 128;

    const int warp_m = (wid & 3) * 32;
    const int warp_n = (wid >> 2) * 64;

    const __half* gb[3] = {
        Ah + (size_t)m0 * KDIM, Al + (size_t)m0 * KDIM,
        Bh + (size_t)n0 * KDIM };

    auto stage = [&](int ck) {
        const uint32_t base = sb + (ck % 3) * STAGE_BYTES;
#pragma unroll
        for (int j = 0; j < 12; j++) {
            const int i   = tid + j * 256;
            const int a   = i >> 10;
            const int rem = i & 1023;
            const int row = rem >> 3;
            const int c16 = rem & 7;
            cpasync16(base + a * 16384 + SWZ(row * 128 + c16 * 16),
                      gb[a] + (size_t)row * KDIM + ck * 64 + c16 * 8);
        }
        asm volatile("cp.async.commit_group;" ::: "memory");
    };

    float acc[2][8][4];
#pragma unroll
    for (int t = 0; t < 2; t++)
#pragma unroll
        for (int n = 0; n < 8; n++)
#pragma unroll
            for (int j = 0; j < 4; j++) acc[t][n][j] = 0.f;

    const int a_row  = warp_m + (lane & 15);
    const int a_half = lane >> 4;
    const int b_row  = warp_n + ((lane >> 4) & 1) * 8 + (lane & 7);
    const int b_half = (lane >> 3) & 1;

    stage(0);
    stage(1);

    for (int c = 0; c < NCH; c++) {
        asm volatile("cp.async.wait_group 1;" ::: "memory");
        __syncthreads();
        if (c + 2 < NCH) stage(c + 2);
        else asm volatile("cp.async.commit_group;" ::: "memory");

        const uint32_t bAh = sb + (c % 3) * STAGE_BYTES;
        const uint32_t bAl = bAh + 16384;
        const uint32_t bBh = bAh + 32768;

#pragma unroll
        for (int ks = 0; ks < 4; ks++) {
            uint32_t ah[2][4], al[2][4], bh[4][4];
#pragma unroll
            for (int t = 0; t < 2; t++) {
                const int r  = a_row + t * 16;
                const uint32_t off =
                    r * 128 + (((ks * 2 + a_half) ^ (r & 7)) * 16);
                ldsm4(ah[t], bAh + off);
                ldsm4(al[t], bAl + off);
            }
#pragma unroll
            for (int p = 0; p < 4; p++) {
                const int r  = b_row + p * 16;
                const uint32_t off =
                    r * 128 + (((ks * 2 + b_half) ^ (r & 7)) * 16);
                ldsm4(bh[p], bBh + off);
            }
#pragma unroll
            for (int t = 0; t < 2; t++)
#pragma unroll
                for (int n = 0; n < 8; n++) {
                    const uint32_t* bhp = &bh[n >> 1][(n & 1) * 2];
                    mma16816(acc[t][n], ah[t], bhp);
                    mma16816(acc[t][n], al[t], bhp);
                }
        }
    }
    __syncthreads();

    const int g  = lane >> 2;
    const int tg = lane & 3;
#pragma unroll
    for (int t = 0; t < 2; t++)
#pragma unroll
        for (int n = 0; n < 8; n++) {
            const int col = n0 + warp_n + n * 8 + tg * 2;
            float* d0 = C + (size_t)(m0 + warp_m + t * 16 + g) * ldc + col;
            float* d1 = C + (size_t)(m0 + warp_m + t * 16 + g + 8) * ldc + col;
            *(float2*)d0 = make_float2(acc[t][n][0], acc[t][n][1]);
            *(float2*)d1 = make_float2(acc[t][n][2], acc[t][n][3]);
        }
}

// ---------------------------------------------------------------------------
// fp32 -> (hi, lo) fp16 split with optional prescale
// ---------------------------------------------------------------------------
__global__ void split_kernel(const float4* __restrict__ in,
                             __half2* __restrict__ hi,
                             __half2* __restrict__ lo, int n4, float scale)
{
    int i = blockIdx.x * blockDim.x + threadIdx.x;
    if (i >= n4) return;
    float4 v = in[i];
    v.x *= scale; v.y *= scale; v.z *= scale; v.w *= scale;
    __half hx = __float2half(v.x), hy = __float2half(v.y);
    __half hz = __float2half(v.z), hw = __float2half(v.w);
    __half lx = __float2half(v.x - __half2float(hx));
    __half ly = __float2half(v.y - __half2float(hy));
    __half lz = __float2half(v.z - __half2float(hz));
    __half lw = __float2half(v.w - __half2float(hw));
    hi[2 * i]     = __halves2half2(hx, hy);
    hi[2 * i + 1] = __halves2half2(hz, hw);
    lo[2 * i]     = __halves2half2(lx, ly);
    lo[2 * i + 1] = __halves2half2(lz, lw);
}

// ---------------------------------------------------------------------------
// W[K,N] fp32 -> W^T fp16 [N,K]  (tiled transpose)
// ---------------------------------------------------------------------------
__global__ void tsplit_kernel(const float* __restrict__ W,
                              __half* __restrict__ Th, int K, int N)
{
    __shared__ float t[32][33];
    const int n0 = blockIdx.x * 32, k0 = blockIdx.y * 32;
    const int tx = threadIdx.x, ty = threadIdx.y;
#pragma unroll
    for (int j = 0; j < 32; j += 8)
        t[ty + j][tx] = W[(size_t)(k0 + ty + j) * N + n0 + tx];
    __syncthreads();
#pragma unroll
    for (int j = 0; j < 32; j += 8) {
        const int r = ty + j;
        Th[(size_t)(n0 + r) * K + k0 + tx] = __float2half(t[tx][r]);
    }
}

// ---------------------------------------------------------------------------
// RoPE in-place on T laid out [S, nheads*HD]
// ---------------------------------------------------------------------------
__global__ void rope_kernel(float* __restrict__ T,
                            const float* __restrict__ cosT,
                            const float* __restrict__ sinT,
                            int nheads, int total)
{
    int idx = blockIdx.x * blockDim.x + threadIdx.x;
    if (idx >= total) return;
    int i = idx & 63;
    int h = (idx >> 6) % nheads;
    int s = idx / (nheads * 64);
    float c  = cosT[s * 64 + i];
    float sn = sinT[s * 64 + i];
    float* p = T + (size_t)s * nheads * HD + h * HD + 2 * i;
    float e = p[0], o = p[1];
    p[0] = e * c - o * sn;
    p[1] = e * sn + o * c;
}

// ---------------------------------------------------------------------------
// mma.sync flash attention, sliding window GQA.
// Block = (head, 128 q rows); 8 warps, each m16 across all 32 keys of a tile.
// QK: 3-term fp16 split (fp32 acc). PV: P fp16 from regs, V 2-term split,
// ldmatrix.trans for V^T fragments. Q in smem (staged once), K/V triple-
// buffered cp.async. 1/sqrt(HD) prefolded into Q.
// ---------------------------------------------------------------------------
#define ATT_QB   32768
#define ATT_KVB  32768
#define ATT_SMEM (2 * ATT_QB + 3 * ATT_KVB)

__global__ __launch_bounds__(256, 1)
void attn_mma(const __half* __restrict__ Qh_, const __half* __restrict__ Ql_,
              const __half* __restrict__ Kh_, const __half* __restrict__ Kl_,
              const __half* __restrict__ Vh_, const __half* __restrict__ Vl_,
              float* __restrict__ O)
{
    extern __shared__ char smem[];
    const uint32_t sb = smem_u32(smem);
    const int h   = blockIdx.x;
    const int q0  = blockIdx.y * 128;
    const int tid = threadIdx.x;
    const int wid = tid >> 5;
    const int lane = tid & 31;
    const int kvh = h >> 2;
    const int warp_m = wid * 16;
    const int g  = lane >> 2;
    const int tg = lane & 3;

    // ---- stage Q (once, part of cp.async group 0) ----
    {
        const __half* qs[2] = { Qh_ + (size_t)q0 * (NQ * HD) + h * HD,
                                Ql_ + (size_t)q0 * (NQ * HD) + h * HD };
#pragma unroll
        for (int j = 0; j < 16; j++) {
            const int i   = tid + j * 256;
            const int arr = i >> 11;
            const int rem = i & 2047;
            const int row = rem >> 4;
            const int c16 = rem & 15;
            cpasync16(sb + arr * ATT_QB + swz256(row, c16),
                      qs[arr] + (size_t)row * (NQ * HD) + c16 * 8);
        }
    }

    int kv_begin = q0 - WINDOW + 1;
    if (kv_begin < 0) kv_begin = 0;
    kv_begin &= ~31;
    const int NT = (q0 + 128 - kv_begin) >> 5;

    const __half* kvsrc[4] = { Kh_, Kl_, Vh_, Vl_ };
    auto stageKV = [&](int t) {
        const uint32_t base = sb + 2 * ATT_QB + (t % 3) * ATT_KVB;
        const int kv0 = kv_begin + t * 32;
#pragma unroll
        for (int j = 0; j < 8; j++) {
            const int i   = tid + j * 256;
            const int arr = i >> 9;
            const int rem = i & 511;
            const int row = rem >> 4;
            const int c16 = rem & 15;
            cpasync16(base + arr * 8192 + swz256(row, c16),
                      kvsrc[arr] + (size_t)(kv0 + row) * (NKV * HD) +
                          kvh * HD + c16 * 8);
        }
        asm volatile("cp.async.commit_group;" ::: "memory");
    };

    stageKV(0);   // group 0 = {Q, tile0}
    stageKV(1);   // group 1 = {tile1}

    float o[16][4];
#pragma unroll
    for (int n = 0; n < 16; n++)
#pragma unroll
        for (int j = 0; j < 4; j++) o[n][j] = 0.f;
    float m0 = -5e29f, m1 = -5e29f, l0 = 0.f, l1 = 0.f;

    const int wq0 = q0 + warp_m;
    const int a_row  = warp_m + (lane & 15);
    const int a_half = lane >> 4;
    const int b_row  = ((lane >> 4) & 1) * 8 + (lane & 7);
    const int b_half = (lane >> 3) & 1;
    const int v_row  = (lane & 7) + ((lane >> 3) & 1) * 8;
    const int v_csel = (lane >> 4) & 1;

    for (int t = 0; t < NT; t++) {
        asm volatile("cp.async.wait_group 1;" ::: "memory");
        __syncthreads();
        if (t + 2 < NT) stageKV(t + 2);
        else asm volatile("cp.async.commit_group;" ::: "memory");

        const int kv0 = kv_begin + t * 32;
        const bool active =
            (kv0 <= wq0 + 15) && (kv0 + 31 >= wq0 - (WINDOW - 1));
        if (active) {
            const uint32_t kvb = sb + 2 * ATT_QB + (t % 3) * ATT_KVB;
            float s[4][4];
#pragma unroll
            for (int n = 0; n < 4; n++)
#pragma unroll
                for (int j = 0; j < 4; j++) s[n][j] = 0.f;

            // ---- S = Q K^T (3 terms) ----
#pragma unroll
            for (int ks = 0; ks < 8; ks++) {
                uint32_t aqh[4], aql[4], kh0[4], kh1[4], kl0[4], kl1[4];
                {
                    const uint32_t off = swz256(a_row, ks * 2 + a_half);
                    ldsm4(aqh, sb + off);
                    ldsm4(aql, sb + ATT_QB + off);
                }
                {
                    const int c16 = ks * 2 + b_half;
                    const uint32_t o0 = swz256(b_row, c16);
                    const uint32_t o1 = swz256(b_row + 16, c16);
                    ldsm4(kh0, kvb + o0);
                    ldsm4(kh1, kvb + o1);
                    ldsm4(kl0, kvb + 8192 + o0);
                    ldsm4(kl1, kvb + 8192 + o1);
                }
                mma16816(s[0], aqh, &kh0[0]);
                mma16816(s[0], aql, &kh0[0]);
                mma16816(s[0], aqh, &kl0[0]);
                mma16816(s[1], aqh, &kh0[2]);
                mma16816(s[1], aql, &kh0[2]);
                mma16816(s[1], aqh, &kl0[2]);
                mma16816(s[2], aqh, &kh1[0]);
                mma16816(s[2], aql, &kh1[0]);
                mma16816(s[2], aqh, &kl1[0]);
                mma16816(s[3], aqh, &kh1[2]);
                mma16816(s[3], aql, &kh1[2]);
                mma16816(s[3], aqh, &kl1[2]);
            }

            // ---- mask + online softmax (rows g / g+8) ----
            float mx0 = -5e29f, mx1 = -5e29f;
#pragma unroll
            for (int n = 0; n < 4; n++)
#pragma unroll
                for (int j = 0; j < 4; j++) {
                    const int key = kv0 + n * 8 + tg * 2 + (j & 1);
                    const int qq  = wq0 + g + (j >> 1) * 8;
                    const int dlt = qq - key;
                    const float v =
                        (dlt >= 0 && dlt < WINDOW) ? s[n][j] : -1e30f;
                    s[n][j] = v;
                    if (j < 2) mx0 = fmaxf(mx0, v);
                    else       mx1 = fmaxf(mx1, v);
                }
            mx0 = fmaxf(mx0, __shfl_xor_sync(0xffffffffu, mx0, 1));
            mx0 = fmaxf(mx0, __shfl_xor_sync(0xffffffffu, mx0, 2));
            mx1 = fmaxf(mx1, __shfl_xor_sync(0xffffffffu, mx1, 1));
            mx1 = fmaxf(mx1, __shfl_xor_sync(0xffffffffu, mx1, 2));

            const float nm0 = fmaxf(m0, mx0);
            const float nm1 = fmaxf(m1, mx1);
            const float al0 = __expf(m0 - nm0);
            const float al1 = __expf(m1 - nm1);
            float ps0 = 0.f, ps1 = 0.f;
#pragma unroll
            for (int n = 0; n < 4; n++) {
                s[n][0] = __expf(s[n][0] - nm0); ps0 += s[n][0];
                s[n][1] = __expf(s[n][1] - nm0); ps0 += s[n][1];
                s[n][2] = __expf(s[n][2] - nm1); ps1 += s[n][2];
                s[n][3] = __expf(s[n][3] - nm1); ps1 += s[n][3];
            }
            ps0 += __shfl_xor_sync(0xffffffffu, ps0, 1);
            ps0 += __shfl_xor_sync(0xffffffffu, ps0, 2);
            ps1 += __shfl_xor_sync(0xffffffffu, ps1, 1);
            ps1 += __shfl_xor_sync(0xffffffffu, ps1, 2);
            l0 = l0 * al0 + ps0;
            l1 = l1 * al1 + ps1;
            m0 = nm0; m1 = nm1;
#pragma unroll
            for (int n = 0; n < 16; n++) {
                o[n][0] *= al0; o[n][1] *= al0;
                o[n][2] *= al1; o[n][3] *= al1;
            }

            // ---- P fragments directly from registers ----
            uint32_t pa[2][4];
#pragma unroll
            for (int ks = 0; ks < 2; ks++) {
                const int n0f = ks * 2;
                __half2 h0 = __floats2half2_rn(s[n0f][0], s[n0f][1]);
                __half2 h1 = __floats2half2_rn(s[n0f][2], s[n0f][3]);
                __half2 h2v = __floats2half2_rn(s[n0f + 1][0], s[n0f + 1][1]);
                __half2 h3 = __floats2half2_rn(s[n0f + 1][2], s[n0f + 1][3]);
                pa[ks][0] = *(uint32_t*)&h0;
                pa[ks][1] = *(uint32_t*)&h1;
                pa[ks][2] = *(uint32_t*)&h2v;
                pa[ks][3] = *(uint32_t*)&h3;
            }

            // ---- O += P V (V = Vh + Vl) ----
#pragma unroll
            for (int ks = 0; ks < 2; ks++) {
                const int krow = ks * 16 + v_row;
#pragma unroll
                for (int nb = 0; nb < 8; nb++) {
                    const uint32_t off = swz256(krow, nb * 2 + v_csel);
                    uint32_t vh[4], vl[4];
                    ldsm4t(vh, kvb + 16384 + off);
                    ldsm4t(vl, kvb + 24576 + off);
                    mma16816(o[nb * 2],     pa[ks], &vh[0]);
                    mma16816(o[nb * 2],     pa[ks], &vl[0]);
                    mma16816(o[nb * 2 + 1], pa[ks], &vh[2]);
                    mma16816(o[nb * 2 + 1], pa[ks], &vl[2]);
                }
            }
        }
    }

    // ---- epilogue ----
    const float inv0 = 1.f / l0;
    const float inv1 = 1.f / l1;
    const int row0 = q0 + warp_m + g;
#pragma unroll
    for (int nb = 0; nb < 16; nb++) {
        const int col = h * HD + nb * 8 + tg * 2;
        *(float2*)&O[(size_t)row0 * DM + col] =
            make_float2(o[nb][0] * inv0, o[nb][1] * inv0);
        *(float2*)&O[(size_t)(row0 + 8) * DM + col] =
            make_float2(o[nb][2] * inv1, o[nb][3] * inv1);
    }
}

// ---------------------------------------------------------------------------
extern "C" void kernel_launch(void* const* d_in, const int* in_sizes, int n_in,
                              void* d_out, int out_size)
{
    const float* x  = (const float*)d_in[0];
    const float* fc = (const float*)d_in[1];
    const float* fs = (const float*)d_in[2];
    const float* wq = (const float*)d_in[4];
    const float* wk = (const float*)d_in[5];
    const float* wv = (const float*)d_in[6];
    const float* wo = (const float*)d_in[7];
    float* out = (float*)d_out;

    float *Qb, *Kb, *Vb, *Ab;
    cudaGetSymbolAddress((void**)&Qb, g_Q);
    cudaGetSymbolAddress((void**)&Kb, g_K);
    cudaGetSymbolAddress((void**)&Vb, g_V);
    cudaGetSymbolAddress((void**)&Ab, g_A);

    __half *xh, *xl, *wqh, *wkh, *wvh, *woh, *ah, *al;
    __half *qh, *ql, *kh, *kl, *vh, *vl;
    cudaGetSymbolAddress((void**)&xh,  g_xh);
    cudaGetSymbolAddress((void**)&xl,  g_xl);
    cudaGetSymbolAddress((void**)&wqh, g_wqh);
    cudaGetSymbolAddress((void**)&wkh, g_wkh);
    cudaGetSymbolAddress((void**)&wvh, g_wvh);
    cudaGetSymbolAddress((void**)&woh, g_woh);
    cudaGetSymbolAddress((void**)&ah,  g_ah);
    cudaGetSymbolAddress((void**)&al,  g_al);
    cudaGetSymbolAddress((void**)&qh,  g_qh);
    cudaGetSymbolAddress((void**)&ql,  g_ql);
    cudaGetSymbolAddress((void**)&kh,  g_kh);
    cudaGetSymbolAddress((void**)&kl,  g_kl);
    cudaGetSymbolAddress((void**)&vh,  g_vh);
    cudaGetSymbolAddress((void**)&vl,  g_vl);

    cudaFuncSetAttribute(gemm_tc, cudaFuncAttributeMaxDynamicSharedMemorySize,
                         GEMM_SMEM);
    cudaFuncSetAttribute(attn_mma, cudaFuncAttributeMaxDynamicSharedMemorySize,
                         ATT_SMEM);

    {
        int n4 = S_LEN * DM / 4;
        split_kernel<<<(n4 + 255) / 256, 256>>>((const float4*)x,
            (__half2*)xh, (__half2*)xl, n4, 1.0f);                           // 0
    }
    tsplit_kernel<<<dim3(DM / 32, DM / 32), dim3(32, 8)>>>(wq, wqh, DM, DM);                 // 1
    tsplit_kernel<<<dim3((NKV * HD) / 32, DM / 32), dim3(32, 8)>>>(wk, wkh, DM, NKV * HD);   // 2

    gemm_tc<<<dim3(DM / 128, S_LEN / 128), 256, GEMM_SMEM>>>(xh, xl, wqh, Qb, DM);           // 3 (profiled)

    tsplit_kernel<<<dim3((NKV * HD) / 32, DM / 32), dim3(32, 8)>>>(wv, wvh, DM, NKV * HD);   // 4
    gemm_tc<<<dim3((NKV * HD) / 128, S_LEN / 128), 256, GEMM_SMEM>>>(xh, xl, wkh, Kb, NKV * HD); // 5
    gemm_tc<<<dim3((NKV * HD) / 128, S_LEN / 128), 256, GEMM_SMEM>>>(xh, xl, wvh, Vb, NKV * HD); // 6
    tsplit_kernel<<<dim3(DM / 32, DM / 32), dim3(32, 8)>>>(wo, woh, DM, DM);                 // 7

    {
        int totq = S_LEN * NQ * (HD / 2);
        int totk = S_LEN * NKV * (HD / 2);
        rope_kernel<<<(totq + 255) / 256, 256>>>(Qb, fc, fs, NQ, totq);      // 8
        rope_kernel<<<(totk + 255) / 256, 256>>>(Kb, fc, fs, NKV, totk);     // 9
    }

    // split Q (prescaled by 1/sqrt(HD)), K, V to fp16 hi/lo
    {
        const float qscale = 0.08838834764831845f;
        int nq4 = S_LEN * NQ * HD / 4;
        int nk4 = S_LEN * NKV * HD / 4;
        split_kernel<<<(nq4 + 255) / 256, 256>>>((const float4*)Qb,
            (__half2*)qh, (__half2*)ql, nq4, qscale);                        // 10
        split_kernel<<<(nk4 + 255) / 256, 256>>>((const float4*)Kb,
            (__half2*)kh, (__half2*)kl, nk4, 1.0f);                          // 11
        split_kernel<<<(nk4 + 255) / 256, 256>>>((const float4*)Vb,
            (__half2*)vh, (__half2*)vl, nk4, 1.0f);                          // 12
    }

    attn_mma<<<dim3(NQ, S_LEN / 128), 256, ATT_SMEM>>>(qh, ql, kh, kl,
                                                       vh, vl, Ab);          // 13

    {
        int n4 = S_LEN * DM / 4;
        split_kernel<<<(n4 + 255) / 256, 256>>>((const float4*)Ab,
            (__half2*)ah, (__half2*)al, n4, 1.0f);                           // 14
    }
    gemm_tc<<<dim3(DM / 128, S_LEN / 128), 256, GEMM_SMEM>>>(ah, al, woh, out, DM);          // 15
}